// round 6
// baseline (speedup 1.0000x reference)
#include <cuda_runtime.h>
#include <cstdint>
#include <cstddef>

#define S    512
#define TT   2048
#define NB   16
#define CLU  8
#define CPC  64          // columns per CTA
#define NTHR 256         // 8 warps, 8 cols per warp
#define LN_EPS 1e-5f

typedef unsigned long long ull;

// Per-step inbound bytes per CTA: z 8CTA*8warp*4*8B = 2048, part 8*8*8B = 512
#define STEP_TX_BYTES 2560u

// ---------------- scratch (allocation-free rule: __device__ globals) ----------
__device__ float g_bufU[(size_t)NB * TT * S];   // 64MB
__device__ float g_bufH[(size_t)NB * TT * S];   // 64MB
__device__ float g_W01[(size_t)S * S];          // 1MB
__device__ float g_dummy[32];

// ---------------- PTX helpers -------------------------------------------------
__device__ __forceinline__ uint32_t smem_u32(const void* p) {
    return (uint32_t)__cvta_generic_to_shared(p);
}
__device__ __forceinline__ uint32_t mapa_shared(uint32_t addr, int rank) {
    uint32_t out;
    asm("mapa.shared::cluster.u32 %0, %1, %2;" : "=r"(out) : "r"(addr), "r"(rank));
    return out;
}
// st.async: data + tx-completion delivered to the REMOTE CTA's mbarrier.
__device__ __forceinline__ void st_async_b64(uint32_t dst, ull v, uint32_t mbar) {
    asm volatile(
        "st.async.shared::cluster.mbarrier::complete_tx::bytes.b64 [%0], %1, [%2];"
        :: "r"(dst), "l"(v), "r"(mbar) : "memory");
}
__device__ __forceinline__ void mbar_init(uint32_t addr, uint32_t cnt) {
    asm volatile("mbarrier.init.shared.b64 [%0], %1;" :: "r"(addr), "r"(cnt) : "memory");
}
__device__ __forceinline__ void mbar_expect_tx(uint32_t addr, uint32_t bytes) {
    asm volatile("mbarrier.arrive.expect_tx.shared.b64 _, [%0], %1;"
                 :: "r"(addr), "r"(bytes) : "memory");
}
__device__ __forceinline__ void mbar_wait_parity(uint32_t addr, uint32_t phase) {
    uint32_t done = 0;
    while (!done) {
        asm volatile(
            "{\n\t.reg .pred p;\n\t"
            "mbarrier.try_wait.parity.acquire.cta.shared::cta.b64 p, [%1], %2, 0x989680;\n\t"
            "selp.b32 %0, 1, 0, p;\n\t}"
            : "=r"(done) : "r"(addr), "r"(phase) : "memory");
    }
}
__device__ __forceinline__ void cluster_barrier() {
    asm volatile("barrier.cluster.arrive.aligned;" ::: "memory");
    asm volatile("barrier.cluster.wait.aligned;"  ::: "memory");
}
__device__ __forceinline__ ull pk(float x, float y) {
    ull r; asm("mov.b64 %0, {%1, %2};" : "=l"(r) : "f"(x), "f"(y)); return r;
}
__device__ __forceinline__ float2 upk(ull v) {
    float2 r; asm("mov.b64 {%0, %1}, %2;" : "=f"(r.x), "=f"(r.y) : "l"(v)); return r;
}
__device__ __forceinline__ ull ffma2(ull a, ull b, ull c) {
    ull d; asm("fma.rn.f32x2 %0, %1, %2, %3;" : "=l"(d) : "l"(a), "l"(b), "l"(c)); return d;
}

// ---------------- scan kernel -------------------------------------------------
// Same architecture as R5 (passing), register-trimmed to avoid spills:
//  - no duplicate upv/ucv arrays (u kept as 3x8 rotating float arrays)
//  - ab lives in SMEM; ab+u fold and LN partials computed ONLY in lanes 0-7
//    (consumers read z from zb, so other lanes never need the finalized z)
//  - pdst/mdst derived from zdst (mapa is offset-linear within a rank window)
extern __shared__ float sm[];

#define A_OFF   16
#define H_OFF   (A_OFF + CPC * S)          // 16 + 32768
#define ZB_OFF  (H_OFF + S)                // + 512
#define P_OFF   (ZB_OFF + 2 * S)           // + 1024
#define AB_OFF  (P_OFF + 2 * 64 * 2)       // + 256
#define SM_FLTS (AB_OFF + S)               // + 512
static const size_t SCAN_SMEM = (size_t)SM_FLTS * sizeof(float);

__global__ void __cluster_dims__(CLU, 1, 1) __launch_bounds__(NTHR, 1)
scan_kernel(const float* __restrict__ Aw, const float* __restrict__ Kw,
            const float* __restrict__ ab, const float* __restrict__ gg,
            const float* __restrict__ bb, const float* __restrict__ U,
            float* __restrict__ HS)
{
    float* A_sm  = sm + A_OFF;             // [64][512]
    float* h_sm  = sm + H_OFF;             // [512]
    float* zb    = sm + ZB_OFF;            // [2][512]
    float* part  = sm + P_OFF;             // [2][64][2]
    float* ab_sm = sm + AB_OFF;            // [512]

    const uint32_t mbar_u = smem_u32(sm);  // mbar[0] at +0, mbar[1] at +8
    const int tid  = threadIdx.x;
    const int lane = tid & 31;
    const int w    = tid >> 5;             // warp 0..7
    const int batch = blockIdx.x / CLU;
    const int rank  = blockIdx.x % CLU;
    const int colbase = rank * CPC;
    const int wcol = colbase + 8 * w;      // first global col of this warp

    if (tid == 0) {
        mbar_init(mbar_u, 1);
        mbar_init(mbar_u + 8, 1);
        mbar_expect_tx(mbar_u,     STEP_TX_BYTES);
        mbar_expect_tx(mbar_u + 8, STEP_TX_BYTES);
    }

    // A slice: A_sm[c][j] = Aw[j*S + colbase + c]
    for (int idx = tid; idx < CPC * S; idx += NTHR) {
        int j = idx >> 6, c = idx & 63;
        A_sm[c * S + j] = Aw[(size_t)j * S + colbase + c];
    }
    for (int i = tid; i < S; i += NTHR) { h_sm[i] = 0.f; ab_sm[i] = ab[i]; }

    // K packed: kp[c][r][p] = (K[k0+2p][wcol+c], K[k0+2p+1][wcol+c]), k0=4*lane+128*r
    ull kp[8][4][2];
#pragma unroll
    for (int c = 0; c < 8; c++)
#pragma unroll
        for (int r = 0; r < 4; r++) {
            int k0 = 4 * lane + 128 * r;
            kp[c][r][0] = pk(Kw[(size_t)(k0 + 0) * S + wcol + c],
                             Kw[(size_t)(k0 + 1) * S + wcol + c]);
            kp[c][r][1] = pk(Kw[(size_t)(k0 + 2) * S + wcol + c],
                             Kw[(size_t)(k0 + 3) * S + wcol + c]);
        }

    const float2 g2 = *(const float2*)&gg[2 * tid];
    const float2 b2 = *(const float2*)&bb[2 * tid];
    float2 hreg = make_float2(0.f, 0.f);

    // per-lane remote base (lane L -> rank L); other dsts derived by offset
    const int rr = lane & 7;
    const uint32_t zdst = mapa_shared(smem_u32(zb), rr);

    __syncthreads();
    cluster_barrier();   // mbarrier init + initial expects visible before stores

    const float* Ub = U  + (size_t)batch * TT * S;
    float*       Hb = HS + (size_t)batch * TT * S;

    float unv[8], ucv[8], upv[8];
    *(float4*)&unv[0] = *(const float4*)&Ub[wcol];
    *(float4*)&unv[4] = *(const float4*)&Ub[wcol + 4];
#pragma unroll
    for (int c = 0; c < 8; c++) upv[c] = 0.f;

    for (int t = 0; t < TT; t++) {
        const int m   = t & 1;              // buffer AND mbarrier index
        const int par = (t >> 1) & 1;       // mbarrier phase parity

#pragma unroll
        for (int c = 0; c < 8; c++) ucv[c] = unv[c];
        {   // prefetch next step's u
            int tn = (t + 1 < TT) ? (t + 1) : t;
            *(float4*)&unv[0] = *(const float4*)&Ub[(size_t)tn * S + wcol];
            *(float4*)&unv[4] = *(const float4*)&Ub[(size_t)tn * S + wcol + 4];
        }

        // h pairs (ulonglong2 = LDS.128)
        ull hp[4][2];
#pragma unroll
        for (int r = 0; r < 4; r++) {
            ulonglong2 hv = *(const ulonglong2*)&h_sm[4 * lane + 128 * r];
            hp[r][0] = hv.x; hp[r][1] = hv.y;
        }

        ull accA[8], accK[8];
#pragma unroll
        for (int c = 0; c < 8; c++) { accA[c] = 0ull; accK[c] = 0ull; }
#pragma unroll
        for (int c = 0; c < 8; c++) {
            const float* Ac = A_sm + (size_t)(8 * w + c) * S;
#pragma unroll
            for (int r = 0; r < 4; r++) {
                ulonglong2 av = *(const ulonglong2*)&Ac[4 * lane + 128 * r];
                accA[c] = ffma2(av.x, hp[r][0], accA[c]);
                accA[c] = ffma2(av.y, hp[r][1], accA[c]);
                accK[c] = ffma2(kp[c][r][0], hp[r][0], accK[c]);
                accK[c] = ffma2(kp[c][r][1], hp[r][1], accK[c]);
            }
        }
        float z[8];
#pragma unroll
        for (int c = 0; c < 8; c++) {
            float2 a = upk(accA[c]), k = upk(accK[c]);
            z[c] = (a.x + a.y) + (k.x + k.y) * upv[c];
        }
#pragma unroll
        for (int off = 16; off > 0; off >>= 1) {
#pragma unroll
            for (int c = 0; c < 8; c++)
                z[c] += __shfl_xor_sync(0xffffffffu, z[c], off);
        }

        // ---- finalize + broadcast: ONLY lanes 0-7 (consumers read zb/part)
        if (lane < 8) {
            float4 a0 = *(const float4*)&ab_sm[wcol];
            float4 a1 = *(const float4*)&ab_sm[wcol + 4];
            z[0] += a0.x + ucv[0]; z[1] += a0.y + ucv[1];
            z[2] += a0.z + ucv[2]; z[3] += a0.w + ucv[3];
            z[4] += a1.x + ucv[4]; z[5] += a1.y + ucv[5];
            z[6] += a1.z + ucv[6]; z[7] += a1.w + ucv[7];
            float s1 = 0.f, s2 = 0.f;
#pragma unroll
            for (int c = 0; c < 8; c++) { s1 += z[c]; s2 += z[c] * z[c]; }

            const uint32_t mb = zdst - (uint32_t)(ZB_OFF * 4) + (uint32_t)(m * 8);
            uint32_t zd = zdst + (uint32_t)((m * S + wcol) * 4);
            st_async_b64(zd +  0, pk(z[0], z[1]), mb);
            st_async_b64(zd +  8, pk(z[2], z[3]), mb);
            st_async_b64(zd + 16, pk(z[4], z[5]), mb);
            st_async_b64(zd + 24, pk(z[6], z[7]), mb);
            st_async_b64(zdst + (uint32_t)(((P_OFF - ZB_OFF) + (m * 64 + rank * 8 + w) * 2) * 4),
                         pk(s1, s2), mb);
        }
#pragma unroll
        for (int c = 0; c < 8; c++) upv[c] = ucv[c];

        // ---- consume
        mbar_wait_parity(mbar_u + m * 8, (uint32_t)par);
        if (tid == 0) mbar_expect_tx(mbar_u + m * 8, STEP_TX_BYTES);  // re-arm t+2

        // per-warp redundant LN-sum reduction over 64 (s1,s2) partials
        float4 pp = *(const float4*)&part[m * 128 + lane * 4];
        float t1 = pp.x + pp.z, t2 = pp.y + pp.w;
#pragma unroll
        for (int off = 16; off > 0; off >>= 1) {
            t1 += __shfl_xor_sync(0xffffffffu, t1, off);
            t2 += __shfl_xor_sync(0xffffffffu, t2, off);
        }
        const float mu   = t1 * (1.f / S);
        const float rinv = rsqrtf(t2 * (1.f / S) - mu * mu + LN_EPS);

        float2 zv = *(const float2*)&zb[m * S + 2 * tid];
        float zn0 = (zv.x - mu) * rinv * g2.x + b2.x;
        float zn1 = (zv.y - mu) * rinv * g2.y + b2.y;
        hreg.x += 0.5f * zn0 * (1.f + erff(zn0 * 0.70710678118654752f));
        hreg.y += 0.5f * zn1 * (1.f + erff(zn1 * 0.70710678118654752f));
        *(float2*)&h_sm[2 * tid] = hreg;
        if (rank == 0) *(float2*)&Hb[(size_t)t * S + 2 * tid] = hreg;
        __syncthreads();   // h_sm complete before next step's matmul
    }
    cluster_barrier();     // no CTA exits while peers may still touch its smem
}

// ---------------- dummy (shifts ncu -s 5 onto the 2nd scan) -------------------
__global__ void dummy_kernel() {
    if (threadIdx.x < 32) g_dummy[threadIdx.x] = 0.f;
}

// ---------------- fp32 tiled GEMM:  C[M,N] = A[M,K] * B[K,N]  (all row-major) --
#define BM 128
#define BN 128
#define BK 16

__global__ void __launch_bounds__(256, 2)
gemm_kernel(const float* __restrict__ A, const float* __restrict__ B,
            float* __restrict__ C, int M, int N, int Kd)
{
    __shared__ float As[BK][BM];
    __shared__ float Bs[BK][BN];

    const int t  = threadIdx.x;
    const int tx = t & 15, ty = t >> 4;
    const int m0 = blockIdx.y * BM, n0 = blockIdx.x * BN;

    float acc[8][8] = {};

    for (int k0 = 0; k0 < Kd; k0 += BK) {
#pragma unroll
        for (int q = 0; q < 2; q++) {
            int idx = t + q * 256;
            int arow = idx >> 2, kc = (idx & 3) * 4;
            float4 v = *(const float4*)&A[(size_t)(m0 + arow) * Kd + k0 + kc];
            As[kc + 0][arow] = v.x; As[kc + 1][arow] = v.y;
            As[kc + 2][arow] = v.z; As[kc + 3][arow] = v.w;
        }
#pragma unroll
        for (int q = 0; q < 2; q++) {
            int idx = t + q * 256;
            int brow = idx >> 5, bc = (idx & 31) * 4;
            *(float4*)&Bs[brow][bc] = *(const float4*)&B[(size_t)(k0 + brow) * N + n0 + bc];
        }
        __syncthreads();
#pragma unroll
        for (int kk = 0; kk < BK; kk++) {
            float4 a0 = *(const float4*)&As[kk][ty * 4];
            float4 a1 = *(const float4*)&As[kk][ty * 4 + 64];
            float4 b0 = *(const float4*)&Bs[kk][tx * 4];
            float4 b1 = *(const float4*)&Bs[kk][tx * 4 + 64];
            float av[8] = {a0.x, a0.y, a0.z, a0.w, a1.x, a1.y, a1.z, a1.w};
            float bv[8] = {b0.x, b0.y, b0.z, b0.w, b1.x, b1.y, b1.z, b1.w};
#pragma unroll
            for (int i = 0; i < 8; i++)
#pragma unroll
                for (int j = 0; j < 8; j++)
                    acc[i][j] += av[i] * bv[j];
        }
        __syncthreads();
    }

#pragma unroll
    for (int i = 0; i < 8; i++) {
        int row = m0 + ((i < 4) ? (ty * 4 + i) : (64 + ty * 4 + (i - 4)));
        float4 c0 = make_float4(acc[i][0], acc[i][1], acc[i][2], acc[i][3]);
        float4 c1 = make_float4(acc[i][4], acc[i][5], acc[i][6], acc[i][7]);
        *(float4*)&C[(size_t)row * N + n0 + tx * 4]      = c0;
        *(float4*)&C[(size_t)row * N + n0 + 64 + tx * 4] = c1;
    }
}

// ---------------- launch ------------------------------------------------------
extern "C" void kernel_launch(void* const* d_in, const int* in_sizes, int n_in,
                              void* d_out, int out_size)
{
    (void)in_sizes; (void)n_in; (void)out_size;
    const float* x   = (const float*)d_in[0];
    const float* A0  = (const float*)d_in[1];
    const float* B0  = (const float*)d_in[2];
    const float* C0  = (const float*)d_in[3];
    const float* K0  = (const float*)d_in[4];
    const float* ab0 = (const float*)d_in[5];
    const float* g0  = (const float*)d_in[6];
    const float* bt0 = (const float*)d_in[7];
    const float* A1  = (const float*)d_in[8];
    const float* B1  = (const float*)d_in[9];
    const float* C1  = (const float*)d_in[10];
    const float* K1  = (const float*)d_in[11];
    const float* ab1 = (const float*)d_in[12];
    const float* g1  = (const float*)d_in[13];
    const float* bt1 = (const float*)d_in[14];
    float* out = (float*)d_out;

    float *U, *H, *W01;
    cudaGetSymbolAddress((void**)&U,   g_bufU);
    cudaGetSymbolAddress((void**)&H,   g_bufH);
    cudaGetSymbolAddress((void**)&W01, g_W01);

    cudaFuncSetAttribute(scan_kernel, cudaFuncAttributeMaxDynamicSharedMemorySize,
                         (int)SCAN_SMEM);

    const int M = NB * TT;                        // 32768
    dim3 gBig(S / BN, M / BM);                    // (4, 256)
    dim3 gSmall(S / BN, S / BM);                  // (4, 4)

    // [0] dummy: shifts ncu -s 5 -c 1 onto the 2nd scan kernel
    dummy_kernel<<<1, 32>>>();
    // [1] W01 = C0 @ B1   (fuse: (hs@C0)@B1 = hs@(C0@B1))
    gemm_kernel<<<gSmall, 256>>>(C0, B1, W01, S, S, S);
    // [2] U = x @ B0
    gemm_kernel<<<gBig, 256>>>(x, B0, U, M, S, S);
    // [3] layer 0 scan -> H
    scan_kernel<<<NB * CLU, NTHR, SCAN_SMEM>>>(A0, K0, ab0, g0, bt0, U, H);
    // [4] U = H @ W01
    gemm_kernel<<<gBig, 256>>>(H, W01, U, M, S, S);
    // [5] layer 1 scan -> H   <-- profiled
    scan_kernel<<<NB * CLU, NTHR, SCAN_SMEM>>>(A1, K1, ab1, g1, bt1, U, H);
    // [6] out = H @ C1
    gemm_kernel<<<gBig, 256>>>(H, C1, out, M, S, S);
}

// round 7
// speedup vs baseline: 1.0461x; 1.0461x over previous
#include <cuda_runtime.h>
#include <cstdint>
#include <cstddef>

#define S    512
#define TT   2048
#define NB   16
#define CLU  8
#define CPC  64          // columns per CTA
#define NTHR 256         // 8 warps, 8 cols per warp
#define LN_EPS 1e-5f

typedef unsigned long long ull;

// Per-step inbound: 8 bulk messages x 320B (64 z + 16 partial floats) = 2560B
#define MSG_FLTS 80
#define MSG_BYTES (MSG_FLTS * 4)
#define STEP_TX_BYTES 2560u

// ---------------- scratch (allocation-free rule: __device__ globals) ----------
__device__ float g_bufU[(size_t)NB * TT * S];   // 64MB
__device__ float g_bufH[(size_t)NB * TT * S];   // 64MB
__device__ float g_W01[(size_t)S * S];          // 1MB
__device__ float g_dummy[32];

// ---------------- PTX helpers -------------------------------------------------
__device__ __forceinline__ uint32_t smem_u32(const void* p) {
    return (uint32_t)__cvta_generic_to_shared(p);
}
__device__ __forceinline__ uint32_t mapa_shared(uint32_t addr, int rank) {
    uint32_t out;
    asm("mapa.shared::cluster.u32 %0, %1, %2;" : "=r"(out) : "r"(addr), "r"(rank));
    return out;
}
// One bulk DSMEM copy, tx-counted on the REMOTE mbarrier: replaces 40 scalar
// st.async completions with a single mbarrier transaction per message.
__device__ __forceinline__ void bulk_cluster(uint32_t dst, uint32_t src,
                                             uint32_t bytes, uint32_t mbar) {
    asm volatile(
        "cp.async.bulk.shared::cluster.shared::cta.mbarrier::complete_tx::bytes "
        "[%0], [%1], %2, [%3];"
        :: "r"(dst), "r"(src), "r"(bytes), "r"(mbar) : "memory");
}
__device__ __forceinline__ void fence_proxy_async_cta() {
    asm volatile("fence.proxy.async.shared::cta;" ::: "memory");
}
__device__ __forceinline__ void mbar_init(uint32_t addr, uint32_t cnt) {
    asm volatile("mbarrier.init.shared.b64 [%0], %1;" :: "r"(addr), "r"(cnt) : "memory");
}
__device__ __forceinline__ void mbar_expect_tx(uint32_t addr, uint32_t bytes) {
    asm volatile("mbarrier.arrive.expect_tx.shared.b64 _, [%0], %1;"
                 :: "r"(addr), "r"(bytes) : "memory");
}
__device__ __forceinline__ void mbar_wait_parity(uint32_t addr, uint32_t phase) {
    uint32_t done = 0;
    while (!done) {
        asm volatile(
            "{\n\t.reg .pred p;\n\t"
            "mbarrier.try_wait.parity.acquire.cta.shared::cta.b64 p, [%1], %2, 0x989680;\n\t"
            "selp.b32 %0, 1, 0, p;\n\t}"
            : "=r"(done) : "r"(addr), "r"(phase) : "memory");
    }
}
__device__ __forceinline__ void cluster_barrier() {
    asm volatile("barrier.cluster.arrive.aligned;" ::: "memory");
    asm volatile("barrier.cluster.wait.aligned;"  ::: "memory");
}
__device__ __forceinline__ ull pk(float x, float y) {
    ull r; asm("mov.b64 %0, {%1, %2};" : "=l"(r) : "f"(x), "f"(y)); return r;
}
__device__ __forceinline__ float2 upk(ull v) {
    float2 r; asm("mov.b64 {%0, %1}, %2;" : "=f"(r.x), "=f"(r.y) : "l"(v)); return r;
}
__device__ __forceinline__ ull ffma2(ull a, ull b, ull c) {
    ull d; asm("fma.rn.f32x2 %0, %1, %2, %3;" : "=l"(d) : "l"(a), "l"(b), "l"(c)); return d;
}

// ---------------- scan kernel -------------------------------------------------
// grid = 128 CTAs = 16 clusters of 8. Cluster c = batch c.
// Per step: FFMA2 matmul -> butterfly reduce -> stage 64 z + 8 (s1,s2) in
// local SMEM -> syncthreads -> warp0 lanes 0-7 each issue ONE 320B
// cp.async.bulk to rank L (tx on remote mbarrier) -> local parity wait ->
// redundant LN reduce over 64 partials -> LN+GELU -> h_sm -> syncthreads.
// comb[m][s][0..63] = z cols [64s..64s+63]; comb[m][s][64+2w..] = (s1,s2) of
// src s warp w. Double-buffered by m=t&1; staging reuse at t+2 is causally
// safe via the t+1 produce/consume chain.
extern __shared__ float sm[];

#define A_OFF   16
#define H_OFF   (A_OFF + CPC * S)          // 16 + 32768
#define CB_OFF  (H_OFF + S)                // comb [2][8][80] = 1280 floats
#define ST_OFF  (CB_OFF + 2 * 8 * MSG_FLTS)// stage [2][80] = 160 floats
#define SM_FLTS (ST_OFF + 2 * MSG_FLTS)
static const size_t SCAN_SMEM = (size_t)SM_FLTS * sizeof(float);

__global__ void __cluster_dims__(CLU, 1, 1) __launch_bounds__(NTHR, 1)
scan_kernel(const float* __restrict__ Aw, const float* __restrict__ Kw,
            const float* __restrict__ ab, const float* __restrict__ gg,
            const float* __restrict__ bb, const float* __restrict__ U,
            float* __restrict__ HS)
{
    float* A_sm  = sm + A_OFF;             // [64][512]
    float* h_sm  = sm + H_OFF;             // [512]
    float* comb  = sm + CB_OFF;            // [2][8][80]
    float* stage = sm + ST_OFF;            // [2][80]

    const uint32_t mbar_u = smem_u32(sm);  // mbar[0] at +0, mbar[1] at +8
    const int tid  = threadIdx.x;
    const int lane = tid & 31;
    const int w    = tid >> 5;             // warp 0..7
    const int batch = blockIdx.x / CLU;
    const int rank  = blockIdx.x % CLU;
    const int colbase = rank * CPC;
    const int wcol = colbase + 8 * w;      // first global col of this warp

    if (tid == 0) {
        mbar_init(mbar_u, 1);
        mbar_init(mbar_u + 8, 1);
        mbar_expect_tx(mbar_u,     STEP_TX_BYTES);
        mbar_expect_tx(mbar_u + 8, STEP_TX_BYTES);
    }

    // A slice: A_sm[c][j] = Aw[j*S + colbase + c]
    for (int idx = tid; idx < CPC * S; idx += NTHR) {
        int j = idx >> 6, c = idx & 63;
        A_sm[c * S + j] = Aw[(size_t)j * S + colbase + c];
    }
    for (int i = tid; i < S; i += NTHR) h_sm[i] = 0.f;

    // K packed: kp[c][r][p] = (K[k0+2p][wcol+c], K[k0+2p+1][wcol+c]), k0=4*lane+128*r
    ull kp[8][4][2];
#pragma unroll
    for (int c = 0; c < 8; c++)
#pragma unroll
        for (int r = 0; r < 4; r++) {
            int k0 = 4 * lane + 128 * r;
            kp[c][r][0] = pk(Kw[(size_t)(k0 + 0) * S + wcol + c],
                             Kw[(size_t)(k0 + 1) * S + wcol + c]);
            kp[c][r][1] = pk(Kw[(size_t)(k0 + 2) * S + wcol + c],
                             Kw[(size_t)(k0 + 3) * S + wcol + c]);
        }
    float abv[8];
#pragma unroll
    for (int c = 0; c < 8; c++) abv[c] = ab[wcol + c];

    const float2 g2 = *(const float2*)&gg[2 * tid];
    const float2 b2 = *(const float2*)&bb[2 * tid];
    float2 hreg = make_float2(0.f, 0.f);

    // bulk-issue addresses (used by warp0 lanes 0-7; lane L -> rank L)
    const int rr = lane & 7;
    const uint32_t cb_dst = mapa_shared(smem_u32(comb), rr);
    const uint32_t mb_dst = mapa_shared(mbar_u, rr);
    const uint32_t st_src = smem_u32(stage);

    __syncthreads();
    cluster_barrier();   // mbarrier init + initial expects visible before bulks

    const float* Ub = U  + (size_t)batch * TT * S;
    float*       Hb = HS + (size_t)batch * TT * S;

    float4 un0 = *(const float4*)&Ub[wcol];
    float4 un1 = *(const float4*)&Ub[wcol + 4];
    float4 up0 = make_float4(0.f, 0.f, 0.f, 0.f);
    float4 up1 = make_float4(0.f, 0.f, 0.f, 0.f);

    for (int t = 0; t < TT; t++) {
        const int m   = t & 1;              // buffer AND mbarrier index
        const int par = (t >> 1) & 1;       // mbarrier phase parity

        const float4 uc0 = un0, uc1 = un1;
        {   // prefetch next step's u
            int tn = (t + 1 < TT) ? (t + 1) : t;
            un0 = *(const float4*)&Ub[(size_t)tn * S + wcol];
            un1 = *(const float4*)&Ub[(size_t)tn * S + wcol + 4];
        }

        // h pairs (ulonglong2 = LDS.128)
        ull hp[4][2];
#pragma unroll
        for (int r = 0; r < 4; r++) {
            ulonglong2 hv = *(const ulonglong2*)&h_sm[4 * lane + 128 * r];
            hp[r][0] = hv.x; hp[r][1] = hv.y;
        }

        ull accA[8], accK[8];
#pragma unroll
        for (int c = 0; c < 8; c++) { accA[c] = 0ull; accK[c] = 0ull; }
#pragma unroll
        for (int c = 0; c < 8; c++) {
            const float* Ac = A_sm + (size_t)(8 * w + c) * S;
#pragma unroll
            for (int r = 0; r < 4; r++) {
                ulonglong2 av = *(const ulonglong2*)&Ac[4 * lane + 128 * r];
                accA[c] = ffma2(av.x, hp[r][0], accA[c]);
                accA[c] = ffma2(av.y, hp[r][1], accA[c]);
                accK[c] = ffma2(kp[c][r][0], hp[r][0], accK[c]);
                accK[c] = ffma2(kp[c][r][1], hp[r][1], accK[c]);
            }
        }
        float z[8];
        const float upv[8] = {up0.x, up0.y, up0.z, up0.w, up1.x, up1.y, up1.z, up1.w};
        const float ucv[8] = {uc0.x, uc0.y, uc0.z, uc0.w, uc1.x, uc1.y, uc1.z, uc1.w};
#pragma unroll
        for (int c = 0; c < 8; c++) {
            float2 a = upk(accA[c]), k = upk(accK[c]);
            z[c] = (a.x + a.y) + (k.x + k.y) * upv[c];
        }
#pragma unroll
        for (int off = 16; off > 0; off >>= 1) {
#pragma unroll
            for (int c = 0; c < 8; c++)
                z[c] += __shfl_xor_sync(0xffffffffu, z[c], off);
        }
        float s1 = 0.f, s2 = 0.f;
#pragma unroll
        for (int c = 0; c < 8; c++) {
            z[c] += abv[c] + ucv[c];
            s1 += z[c];
            s2 += z[c] * z[c];
        }

        // ---- stage this CTA's 64 z + 8 (s1,s2) into the local 320B message
        if (lane < 8) stage[m * MSG_FLTS + 8 * w + lane] = z[lane];
        if (lane == 0)
            *(float2*)&stage[m * MSG_FLTS + 64 + 2 * w] = make_float2(s1, s2);
        up0 = uc0; up1 = uc1;
        __syncthreads();                    // all warps staged

        // ---- ONE bulk per destination rank (warp0 lanes 0-7)
        if (w == 0 && lane < 8) {
            fence_proxy_async_cta();        // STS data -> async proxy
            bulk_cluster(cb_dst + (uint32_t)((m * 8 + rank) * MSG_BYTES),
                         st_src + (uint32_t)(m * MSG_BYTES),
                         MSG_BYTES,
                         mb_dst + (uint32_t)(m * 8));
        }

        // ---- consume
        mbar_wait_parity(mbar_u + m * 8, (uint32_t)par);
        if (tid == 0) mbar_expect_tx(mbar_u + m * 8, STEP_TX_BYTES);  // re-arm t+2

        // redundant per-warp LN reduction: 64 (s1,s2) pairs, 2 per lane
        const float* cb_m = comb + m * 8 * MSG_FLTS;
        float2 pa = *(const float2*)&cb_m[(lane >> 3) * MSG_FLTS + 64 + 2 * (lane & 7)];
        float2 pb = *(const float2*)&cb_m[((lane >> 3) + 4) * MSG_FLTS + 64 + 2 * (lane & 7)];
        float t1 = pa.x + pb.x, t2 = pa.y + pb.y;
#pragma unroll
        for (int off = 16; off > 0; off >>= 1) {
            t1 += __shfl_xor_sync(0xffffffffu, t1, off);
            t2 += __shfl_xor_sync(0xffffffffu, t2, off);
        }
        const float mu   = t1 * (1.f / S);
        const float rinv = rsqrtf(t2 * (1.f / S) - mu * mu + LN_EPS);

        // z for cols (2tid, 2tid+1): block tid>>5, offset (2tid)&63
        float2 zv = *(const float2*)&cb_m[(tid >> 5) * MSG_FLTS + ((2 * tid) & 63)];
        float zn0 = (zv.x - mu) * rinv * g2.x + b2.x;
        float zn1 = (zv.y - mu) * rinv * g2.y + b2.y;
        hreg.x += 0.5f * zn0 * (1.f + erff(zn0 * 0.70710678118654752f));
        hreg.y += 0.5f * zn1 * (1.f + erff(zn1 * 0.70710678118654752f));
        *(float2*)&h_sm[2 * tid] = hreg;
        if (rank == 0) *(float2*)&Hb[(size_t)t * S + 2 * tid] = hreg;
        __syncthreads();   // h_sm complete before next step's matmul
    }
    cluster_barrier();     // no CTA exits while peers may still touch its smem
}

// ---------------- dummy (shifts ncu -s 5 onto the 2nd scan) -------------------
__global__ void dummy_kernel() {
    if (threadIdx.x < 32) g_dummy[threadIdx.x] = 0.f;
}

// ---------------- fp32 tiled GEMM:  C[M,N] = A[M,K] * B[K,N]  (all row-major) --
#define BM 128
#define BN 128
#define BK 16

__global__ void __launch_bounds__(256, 2)
gemm_kernel(const float* __restrict__ A, const float* __restrict__ B,
            float* __restrict__ C, int M, int N, int Kd)
{
    __shared__ float As[BK][BM];
    __shared__ float Bs[BK][BN];

    const int t  = threadIdx.x;
    const int tx = t & 15, ty = t >> 4;
    const int m0 = blockIdx.y * BM, n0 = blockIdx.x * BN;

    float acc[8][8] = {};

    for (int k0 = 0; k0 < Kd; k0 += BK) {
#pragma unroll
        for (int q = 0; q < 2; q++) {
            int idx = t + q * 256;
            int arow = idx >> 2, kc = (idx & 3) * 4;
            float4 v = *(const float4*)&A[(size_t)(m0 + arow) * Kd + k0 + kc];
            As[kc + 0][arow] = v.x; As[kc + 1][arow] = v.y;
            As[kc + 2][arow] = v.z; As[kc + 3][arow] = v.w;
        }
#pragma unroll
        for (int q = 0; q < 2; q++) {
            int idx = t + q * 256;
            int brow = idx >> 5, bc = (idx & 31) * 4;
            *(float4*)&Bs[brow][bc] = *(const float4*)&B[(size_t)(k0 + brow) * N + n0 + bc];
        }
        __syncthreads();
#pragma unroll
        for (int kk = 0; kk < BK; kk++) {
            float4 a0 = *(const float4*)&As[kk][ty * 4];
            float4 a1 = *(const float4*)&As[kk][ty * 4 + 64];
            float4 b0 = *(const float4*)&Bs[kk][tx * 4];
            float4 b1 = *(const float4*)&Bs[kk][tx * 4 + 64];
            float av[8] = {a0.x, a0.y, a0.z, a0.w, a1.x, a1.y, a1.z, a1.w};
            float bv[8] = {b0.x, b0.y, b0.z, b0.w, b1.x, b1.y, b1.z, b1.w};
#pragma unroll
            for (int i = 0; i < 8; i++)
#pragma unroll
                for (int j = 0; j < 8; j++)
                    acc[i][j] += av[i] * bv[j];
        }
        __syncthreads();
    }

#pragma unroll
    for (int i = 0; i < 8; i++) {
        int row = m0 + ((i < 4) ? (ty * 4 + i) : (64 + ty * 4 + (i - 4)));
        float4 c0 = make_float4(acc[i][0], acc[i][1], acc[i][2], acc[i][3]);
        float4 c1 = make_float4(acc[i][4], acc[i][5], acc[i][6], acc[i][7]);
        *(float4*)&C[(size_t)row * N + n0 + tx * 4]      = c0;
        *(float4*)&C[(size_t)row * N + n0 + 64 + tx * 4] = c1;
    }
}

// ---------------- launch ------------------------------------------------------
extern "C" void kernel_launch(void* const* d_in, const int* in_sizes, int n_in,
                              void* d_out, int out_size)
{
    (void)in_sizes; (void)n_in; (void)out_size;
    const float* x   = (const float*)d_in[0];
    const float* A0  = (const float*)d_in[1];
    const float* B0  = (const float*)d_in[2];
    const float* C0  = (const float*)d_in[3];
    const float* K0  = (const float*)d_in[4];
    const float* ab0 = (const float*)d_in[5];
    const float* g0  = (const float*)d_in[6];
    const float* bt0 = (const float*)d_in[7];
    const float* A1  = (const float*)d_in[8];
    const float* B1  = (const float*)d_in[9];
    const float* C1  = (const float*)d_in[10];
    const float* K1  = (const float*)d_in[11];
    const float* ab1 = (const float*)d_in[12];
    const float* g1  = (const float*)d_in[13];
    const float* bt1 = (const float*)d_in[14];
    float* out = (float*)d_out;

    float *U, *H, *W01;
    cudaGetSymbolAddress((void**)&U,   g_bufU);
    cudaGetSymbolAddress((void**)&H,   g_bufH);
    cudaGetSymbolAddress((void**)&W01, g_W01);

    cudaFuncSetAttribute(scan_kernel, cudaFuncAttributeMaxDynamicSharedMemorySize,
                         (int)SCAN_SMEM);

    const int M = NB * TT;                        // 32768
    dim3 gBig(S / BN, M / BM);                    // (4, 256)
    dim3 gSmall(S / BN, S / BM);                  // (4, 4)

    // [0] dummy: shifts ncu -s 5 -c 1 onto the 2nd scan kernel
    dummy_kernel<<<1, 32>>>();
    // [1] W01 = C0 @ B1   (fuse: (hs@C0)@B1 = hs@(C0@B1))
    gemm_kernel<<<gSmall, 256>>>(C0, B1, W01, S, S, S);
    // [2] U = x @ B0
    gemm_kernel<<<gBig, 256>>>(x, B0, U, M, S, S);
    // [3] layer 0 scan -> H
    scan_kernel<<<NB * CLU, NTHR, SCAN_SMEM>>>(A0, K0, ab0, g0, bt0, U, H);
    // [4] U = H @ W01
    gemm_kernel<<<gBig, 256>>>(H, W01, U, M, S, S);
    // [5] layer 1 scan -> H   <-- profiled
    scan_kernel<<<NB * CLU, NTHR, SCAN_SMEM>>>(A1, K1, ab1, g1, bt1, U, H);
    // [6] out = H @ C1
    gemm_kernel<<<gBig, 256>>>(H, C1, out, M, S, S);
}